// round 15
// baseline (speedup 1.0000x reference)
#include <cuda_runtime.h>
#include <cuda_fp16.h>
#include <cstdint>
#include <cstddef>

// MultiDecoder: A=10 MLPs 12->128->256->200 over 32768 tokens.
// fp32 scalar layer1 + single-pass fp16 mma.sync (m16n8k16) layers 2 & 3.
// R15: cut smem crossbar traffic (L1 was 70% vs tensor 36%) -- 4 warps/CTA,
// each warp owns ALL 64 m-rows x 8 n-tiles (layer2; 7/6/6/6 in layer3).
// ldsm bytes/chunk: 48KB -> 32KB (A-frag reuse 4x -> 8x). 128 regs of cacc,
// __launch_bounds__(128,2) -> 2 CTAs/SM (8 warps/SM, RF exactly full).
// Warp-private B pipelines (no barriers in GEMM loops), 3-stage ring.

#define NA 10
#define NC 12
#define NH2 128
#define NH 256
#define NF 200
#define NL 120
#define NTOK 32768
#define TM 64
#define NTHR 128

// smem layout (bytes):
//   A plane:  [64 rows][512B, 16B-XOR swizzle]        = 32768  @ 0
//   B stages: [3 stages][4 warps][64 rows][80B pitch] = 61440  @ 32768
//   s_w1:     12*128 floats                           = 6144   @ 94208
#define OFF_BST 32768
#define BWSLOT 5120                    // 64 rows * 80B, per warp per stage
#define BSTAGE (4 * BWSLOT)            // 20480
#define OFF_W1 94208
#define SMEM_REQ 100352

#define ASWZ(row, byte) ((unsigned)(byte) ^ (((unsigned)(row) & 7u) << 4))

// weights fp16, pre-transposed to [n][k]
__device__ __align__(16) __half g_w2t[NA * 256 * 128];  // [a][n=256][k=128]
__device__ __align__(16) __half g_w3t[NA * 200 * 256];  // [a][n=200][k=256]

// ---------------- PTX helpers (base-target only) ----------------
__device__ __forceinline__ void mma_f16(float* c, const unsigned* a, const unsigned* b) {
    asm("mma.sync.aligned.m16n8k16.row.col.f32.f16.f16.f32 "
        "{%0,%1,%2,%3}, {%4,%5,%6,%7}, {%8,%9}, {%0,%1,%2,%3};"
        : "+f"(c[0]), "+f"(c[1]), "+f"(c[2]), "+f"(c[3])
        : "r"(a[0]), "r"(a[1]), "r"(a[2]), "r"(a[3]), "r"(b[0]), "r"(b[1]));
}
__device__ __forceinline__ void ldsm_x4(unsigned* r, uint32_t addr) {
    asm volatile("ldmatrix.sync.aligned.m8n8.x4.shared.b16 {%0,%1,%2,%3}, [%4];"
                 : "=r"(r[0]), "=r"(r[1]), "=r"(r[2]), "=r"(r[3]) : "r"(addr));
}
__device__ __forceinline__ void ldsm_x2(unsigned* r, uint32_t addr) {
    asm volatile("ldmatrix.sync.aligned.m8n8.x2.shared.b16 {%0,%1}, [%2];"
                 : "=r"(r[0]), "=r"(r[1]) : "r"(addr));
}
__device__ __forceinline__ void cpa16(uint32_t dst, const void* src) {
    asm volatile("cp.async.cg.shared.global [%0], [%1], 16;" ::"r"(dst), "l"(src) : "memory");
}
#define CP_COMMIT() asm volatile("cp.async.commit_group;" ::: "memory")
#define CP_WAITN(n) asm volatile("cp.async.wait_group %0;" ::"n"(n) : "memory")

__device__ __forceinline__ uint32_t pack2h(float lo_f, float hi_f) {
    uint32_t r;
    asm("cvt.rn.f16x2.f32 %0, %1, %2;" : "=r"(r) : "f"(hi_f), "f"(lo_f));
    return r;
}

// ---------------- fused prep kernel: fp16 convert + transpose ----------------
#define N_W2 (NA * 256 * 128)
#define N_W3 (NA * 200 * 256)
__global__ void prep_w(const float* __restrict__ W2, const float* __restrict__ W3) {
    int i = blockIdx.x * 256 + threadIdx.x;
    if (i < N_W2) {
        int k = i & 127, n = (i >> 7) & 255, a = i >> 15;
        g_w2t[((size_t)a * 256 + n) * 128 + k] =
            __float2half_rn(W2[((size_t)a * NH2 + k) * NH + n]);
    } else if (i < N_W2 + N_W3) {
        int j = i - N_W2;
        int k = j & 255, n = (j >> 8) % 200, a = j / (200 * 256);
        g_w3t[((size_t)a * 200 + n) * 256 + k] =
            __float2half_rn(W3[((size_t)a * NH + k) * NF + n]);
    }
}

// ---------------- warp-private B slice loader (32 lanes, own commit group) ----
__device__ __forceinline__ void warp_load_b(uint32_t dstU, const __half* src,
                                            int Kst, int rows, int lane) {
#pragma unroll
    for (int it = 0; it < 8; it++) {
        int i = it * 32 + lane;
        if (i < rows * 4) {
            int r = i >> 2, seg = i & 3;
            cpa16(dstU + (unsigned)(r * 80 + seg * 16), src + (size_t)r * Kst + seg * 8);
        }
    }
    CP_COMMIT();
}

// ---------------- chunk load dispatch by global chunk id q (0..11) ----------
__device__ __forceinline__ void load_chunk_q(int q, uint32_t bslot0,
                                             const __half* w2w, const __half* w3w,
                                             int rows3, int lane) {
    uint32_t st = bslot0 + (q % 3) * BSTAGE;
    if (q < 4) warp_load_b(st, w2w + (size_t)q * 32, 128, 64, lane);
    else       warp_load_b(st, w3w + (size_t)(q - 4) * 32, 256, rows3, lane);
}

// ---------------- one k=32 chunk over the warp's private slice ----------------
// Warp covers all 64 m-rows (4 m-tiles) x NT n-tiles (8 / 7 / 6).
template <int NT>
__device__ __forceinline__ void gemm_chunk(float (&c)[4][8][4], uint32_t su,
                                           uint32_t bSlot, int kc, int lane) {
#pragma unroll
    for (int ks = 0; ks < 2; ks++) {
        const int k0 = kc + ks * 16;
        unsigned af[4][4];
#pragma unroll
        for (int mt = 0; mt < 4; mt++) {
            int row = mt * 16 + (lane & 15);
            ldsm_x4(af[mt], su + (unsigned)(row * 512) +
                                ASWZ(row, (k0 + ((lane >> 4) << 3)) * 2));
        }
        unsigned bf[16];
#pragma unroll
        for (int p = 0; p < NT / 2; p++) {
            ldsm_x4(bf + 4 * p,
                    bSlot + (unsigned)((p * 16 + (lane & 7) + ((lane >> 4) << 3)) * 80 +
                                       ks * 32 + (((lane >> 3) & 1) << 4)));
        }
        if (NT & 1) {
            ldsm_x2(bf + 2 * (NT - 1),
                    bSlot + (unsigned)(((NT - 1) * 8 + (lane & 7)) * 80 +
                                       ks * 32 + (((lane >> 3) & 1) << 4)));
        }
#pragma unroll
        for (int j = 0; j < NT; j++)
#pragma unroll
            for (int mt = 0; mt < 4; mt++)
                mma_f16(c[mt][j], af[mt], bf + 2 * j);
    }
}

// ---------------- main kernel ----------------
__global__ void __launch_bounds__(NTHR, 2)
main_kernel(const float* __restrict__ x, const float* __restrict__ W1,
            const float* __restrict__ b1, const float* __restrict__ b2,
            const float* __restrict__ b3, const int* __restrict__ idx,
            float* __restrict__ out) {
    extern __shared__ char smem[];
    const uint32_t su = (uint32_t)__cvta_generic_to_shared(smem);

    const int a = blockIdx.y;
    const int n0 = blockIdx.x * TM;
    const int tid = threadIdx.x;
    const int wid = tid >> 5;
    const int lane = tid & 31;
    const int g = lane >> 2, tg = lane & 3;

    // n ownership: layer2 = 64 cols @ wid*64 (8 tiles);
    // layer3 tiles: wid0: 7 @ 0; wid1-3: 6 @ 7/13/19.
    const int nb2 = wid * 64;
    const int t3base = (wid == 0) ? 0 : (1 + wid * 6);   // 0,7,13,19
    const int nt3 = (wid == 0) ? 7 : 6;

    const __half* w2w = g_w2t + (size_t)a * 256 * 128 + (size_t)nb2 * 128;
    const __half* w3w = g_w3t + (size_t)a * 200 * 256 + (size_t)t3base * 8 * 256;
    const int rows3 = nt3 * 8;

    const uint32_t bslot0 = su + OFF_BST + wid * BWSLOT;

    // ---- prologue: prefetch depth 2 -- chunks q=0 (stage0), q=1 (stage1) ----
    load_chunk_q(0, bslot0, w2w, w3w, rows3, lane);
    load_chunk_q(1, bslot0, w2w, w3w, rows3, lane);

    // ---- stage W1 ----
    float* s_w1 = (float*)(smem + OFF_W1);   // [12][128]
    for (int i = tid; i < NC * NH2; i += NTHR) s_w1[i] = W1[a * NC * NH2 + i];
    __syncthreads();                                       // barrier 1

    // ---- layer 1 (fp32 scalar): h1 = relu(xg@W1+b1) -> A plane (fp16) ----
    {
        const int t = tid & 63;
        const int hb = (tid >> 6) * 64;      // 2 groups of 64 h-values
        const int* idxa = idx + a * NC;
        float xv[NC];
#pragma unroll
        for (int c = 0; c < NC; c++)
            xv[c] = __ldg(&x[(size_t)(n0 + t) * NL + __ldg(&idxa[c])]);
        float acc[64];
#pragma unroll
        for (int j = 0; j < 64; j++) acc[j] = __ldg(&b1[a * NH2 + hb + j]);
#pragma unroll
        for (int c = 0; c < NC; c++) {
            const float4* wr = (const float4*)(s_w1 + c * NH2 + hb);
#pragma unroll
            for (int q = 0; q < 16; q++) {
                float4 w = wr[q];
                acc[q * 4 + 0] = fmaf(xv[c], w.x, acc[q * 4 + 0]);
                acc[q * 4 + 1] = fmaf(xv[c], w.y, acc[q * 4 + 1]);
                acc[q * 4 + 2] = fmaf(xv[c], w.z, acc[q * 4 + 2]);
                acc[q * 4 + 3] = fmaf(xv[c], w.w, acc[q * 4 + 3]);
            }
        }
        char* rowp = smem + (size_t)t * 512;
#pragma unroll
        for (int q = 0; q < 32; q++) {
            float v0 = fmaxf(acc[2 * q], 0.0f), v1 = fmaxf(acc[2 * q + 1], 0.0f);
            *(uint32_t*)(rowp + ASWZ(t, hb * 2 + q * 4)) = pack2h(v0, v1);
        }
    }
    __syncthreads();                                       // barrier 2: A2 ready

    float cacc[4][8][4];
#pragma unroll
    for (int mt = 0; mt < 4; mt++)
#pragma unroll
        for (int j = 0; j < 8; j++)
#pragma unroll
            for (int q = 0; q < 4; q++) cacc[mt][j][q] = 0.0f;

    // ---- layer 2: chunks q=0..3, warp-private pipeline, NO barriers ----
    for (int q = 0; q < 4; q++) {
        CP_WAITN(1);
        if (q + 2 < 12) load_chunk_q(q + 2, bslot0, w2w, w3w, rows3, lane);
        gemm_chunk<8>(cacc, su, bslot0 + (q % 3) * BSTAGE, q * 32, lane);
    }

    // ---- epilogue 2: bias+relu -> A3 plane (overwrites A2, fp16) ----
    __syncthreads();                                       // barrier 3: A2 reads done
    {
#pragma unroll
        for (int mt = 0; mt < 4; mt++) {
#pragma unroll
            for (int j = 0; j < 8; j++) {
                int col = nb2 + j * 8 + tg * 2;
                float bb0 = __ldg(&b2[a * NH + col]);
                float bb1 = __ldg(&b2[a * NH + col + 1]);
                int r0 = mt * 16 + g;
#pragma unroll
                for (int half = 0; half < 2; half++) {
                    int r = r0 + half * 8;
                    float v0 = fmaxf(cacc[mt][j][2 * half + 0] + bb0, 0.0f);
                    float v1 = fmaxf(cacc[mt][j][2 * half + 1] + bb1, 0.0f);
                    *(uint32_t*)(smem + (size_t)r * 512 + ASWZ(r, col * 2)) =
                        pack2h(v0, v1);
                }
            }
        }
    }
    __syncthreads();                                       // barrier 4: A3 ready

#pragma unroll
    for (int mt = 0; mt < 4; mt++)
#pragma unroll
        for (int j = 0; j < 8; j++)
#pragma unroll
            for (int q = 0; q < 4; q++) cacc[mt][j][q] = 0.0f;

    // ---- layer 3: chunks q=4..11, warp-private pipeline, NO barriers ----
    for (int q = 4; q < 12; q++) {
        if (q <= 10) CP_WAITN(1);     // pending {q,q+1} -> q done
        else CP_WAITN(0);             // pending {11}    -> 11 done
        if (q + 2 < 12) load_chunk_q(q + 2, bslot0, w2w, w3w, rows3, lane);
        if (nt3 == 7)
            gemm_chunk<7>(cacc, su, bslot0 + (q % 3) * BSTAGE, (q - 4) * 32, lane);
        else
            gemm_chunk<6>(cacc, su, bslot0 + (q % 3) * BSTAGE, (q - 4) * 32, lane);
    }

    // ---- epilogue 3: bias add, store fragments directly (f32 out) ----
    {
#pragma unroll
        for (int mt = 0; mt < 4; mt++) {
#pragma unroll
            for (int j = 0; j < 7; j++) {
                if (j < nt3) {
                    int col = (t3base + j) * 8 + tg * 2;
                    float bb0 = __ldg(&b3[a * NF + col]);
                    float bb1 = __ldg(&b3[a * NF + col + 1]);
                    int r0 = mt * 16 + g;
#pragma unroll
                    for (int half = 0; half < 2; half++) {
                        int r = r0 + half * 8;
                        float2 v = make_float2(cacc[mt][j][2 * half + 0] + bb0,
                                               cacc[mt][j][2 * half + 1] + bb1);
                        *(float2*)&out[((size_t)(n0 + r) * NA + a) * NF + col] = v;
                    }
                }
            }
        }
    }
}

// ---------------- launch ----------------
extern "C" void kernel_launch(void* const* d_in, const int* in_sizes, int n_in,
                              void* d_out, int out_size) {
    const float *x = nullptr, *W1 = nullptr, *b1 = nullptr, *W2 = nullptr,
                *b2 = nullptr, *W3 = nullptr, *b3 = nullptr;
    const int* idx = nullptr;
    for (int i = 0; i < n_in; i++) {
        switch (in_sizes[i]) {
            case NTOK * NL:     x   = (const float*)d_in[i]; break;
            case NA * NC * NH2: W1  = (const float*)d_in[i]; break;
            case NA * NH2:      b1  = (const float*)d_in[i]; break;
            case NA * NH2 * NH: W2  = (const float*)d_in[i]; break;
            case NA * NH:       b2  = (const float*)d_in[i]; break;
            case NA * NH * NF:  W3  = (const float*)d_in[i]; break;
            case NA * NF:       b3  = (const float*)d_in[i]; break;
            case NA * NC:       idx = (const int*)d_in[i];   break;
            default: break;
        }
    }

    prep_w<<<(N_W2 + N_W3 + 255) / 256, 256>>>(W2, W3);

    cudaFuncSetAttribute(main_kernel,
                         cudaFuncAttributeMaxDynamicSharedMemorySize, SMEM_REQ);
    dim3 grid(NTOK / TM, NA);
    main_kernel<<<grid, NTHR, SMEM_REQ>>>(x, W1, b1, b2, b3, idx, (float*)d_out);
}

// round 17
// speedup vs baseline: 1.2121x; 1.2121x over previous
#include <cuda_runtime.h>
#include <cuda_fp16.h>
#include <cstdint>
#include <cstddef>

// MultiDecoder: A=10 MLPs 12->128->256->200 over 32768 tokens.
// fp32 scalar layer1 + single-pass fp16 mma.sync (m16n8k16) layers 2 & 3.
// R17 (= R16 resubmit after infra failure): B fragments are warp-private ->
// bypass smem entirely. Prep kernel stores B in exact mma-fragment order
// (one uint2 per lane per (tile,kstep)); kernel loads B with coalesced __ldg
// into registers (1-chunk prefetch, ping-pong regs). Crossbar traffic/chunk:
// 64KB -> 32KB (A only). R13 warp layout: 8 warps, each owns all 64 m-rows x
// private n-slice. CTA = (articulator, 64 tokens), 256 threads, 2 CTAs/SM.

#define NA 10
#define NC 12
#define NH2 128
#define NH 256
#define NF 200
#define NL 120
#define NTOK 32768
#define TM 64

// smem layout (bytes): A plane [64 rows][512B, swizzled] @0; s_w1 @32768
#define OFF_W1 32768
#define SMEM_REQ 38912

#define ASWZ(row, byte) ((unsigned)(byte) ^ (((unsigned)(row) & 7u) << 4))

// B in mma-fragment order:
//   g_w2f[a][tile:32][ks:8][lane:32]  (uint2: {k,k+1},{k+8,k+9} f16 pairs)
//   g_w3f[a][tile:25][ks:16][lane:32]
__device__ __align__(16) uint2 g_w2f[NA * 32 * 8 * 32];   // 655360 B
__device__ __align__(16) uint2 g_w3f[NA * 25 * 16 * 32];  // 1024000 B

// ---------------- PTX helpers (base-target only) ----------------
__device__ __forceinline__ void mma_f16(float* c, const unsigned* a, const unsigned* b) {
    asm("mma.sync.aligned.m16n8k16.row.col.f32.f16.f16.f32 "
        "{%0,%1,%2,%3}, {%4,%5,%6,%7}, {%8,%9}, {%0,%1,%2,%3};"
        : "+f"(c[0]), "+f"(c[1]), "+f"(c[2]), "+f"(c[3])
        : "r"(a[0]), "r"(a[1]), "r"(a[2]), "r"(a[3]), "r"(b[0]), "r"(b[1]));
}
__device__ __forceinline__ void ldsm_x4(unsigned* r, uint32_t addr) {
    asm volatile("ldmatrix.sync.aligned.m8n8.x4.shared.b16 {%0,%1,%2,%3}, [%4];"
                 : "=r"(r[0]), "=r"(r[1]), "=r"(r[2]), "=r"(r[3]) : "r"(addr));
}
__device__ __forceinline__ uint32_t pack2h(float lo_f, float hi_f) {
    uint32_t r;
    asm("cvt.rn.f16x2.f32 %0, %1, %2;" : "=r"(r) : "f"(hi_f), "f"(lo_f));
    return r;
}

// ---------------- prep kernel: fp16 fragment layout ----------------
// b0 pair = {W[k][n], W[k+1][n]}, b1 pair = {W[k+8][n], W[k+9][n]},
// n = tile*8 + (lane>>2), k = ks*16 + 2*(lane&3).  (derived from ldsm m8n8
// non-trans semantics on the previously-working [n][k] smem layout)
#define N_F2 (NA * 32 * 8 * 32)     // 81920
#define N_F3 (NA * 25 * 16 * 32)    // 128000
__global__ void prep_w(const float* __restrict__ W2, const float* __restrict__ W3) {
    int i = blockIdx.x * 256 + threadIdx.x;
    if (i < N_F2) {
        int l = i & 31, ks = (i >> 5) & 7, tile = (i >> 8) & 31, a = i >> 13;
        int n = tile * 8 + (l >> 2);
        int k = ks * 16 + 2 * (l & 3);
        const float* W = W2 + (size_t)a * NH2 * NH;     // [k=128][n=256]
        uint2 v;
        v.x = pack2h(W[(size_t)k * NH + n],       W[(size_t)(k + 1) * NH + n]);
        v.y = pack2h(W[(size_t)(k + 8) * NH + n], W[(size_t)(k + 9) * NH + n]);
        g_w2f[i] = v;
    } else if (i < N_F2 + N_F3) {
        int j = i - N_F2;
        int a = j / 12800, r = j % 12800;
        int tile = r >> 9, ks = (r >> 5) & 15, l = r & 31;
        int n = tile * 8 + (l >> 2);
        int k = ks * 16 + 2 * (l & 3);
        const float* W = W3 + (size_t)a * NH * NF;      // [k=256][n=200]
        uint2 v;
        v.x = pack2h(W[(size_t)k * NF + n],       W[(size_t)(k + 1) * NF + n]);
        v.y = pack2h(W[(size_t)(k + 8) * NF + n], W[(size_t)(k + 9) * NF + n]);
        g_w3f[(size_t)a * 12800 + (size_t)tile * 512 + ks * 32 + l] = v;
    }
}

// ---------------- B register loads (coalesced 256B per instruction) --------
// b layout: b[ks*8 + 2*j] = b0 of tile j at kstep ks, b[ks*8+2*j+1] = b1.
__device__ __forceinline__ void load_b2(unsigned* b, const uint2* base2, int q) {
#pragma unroll
    for (int j = 0; j < 4; j++)
#pragma unroll
        for (int s = 0; s < 2; s++) {
            uint2 v = __ldg(base2 + j * 256 + (2 * q + s) * 32);
            b[s * 8 + 2 * j] = v.x;
            b[s * 8 + 2 * j + 1] = v.y;
        }
}
__device__ __forceinline__ void load_b3(unsigned* b, const uint2* base3, int c, int nt) {
#pragma unroll
    for (int j = 0; j < 4; j++)
        if (j < nt)             // warp-uniform
#pragma unroll
            for (int s = 0; s < 2; s++) {
                uint2 v = __ldg(base3 + j * 512 + (2 * c + s) * 32);
                b[s * 8 + 2 * j] = v.x;
                b[s * 8 + 2 * j + 1] = v.y;
            }
}

// ---------------- one k=32 chunk: A from smem, B from registers ------------
// Same accumulation order as R13: ks outer, j, mt inner.
template <int NT>
__device__ __forceinline__ void gemm_chunk(float (&c)[4][4][4], uint32_t su,
                                           const unsigned* b, int kc, int lane) {
#pragma unroll
    for (int ks = 0; ks < 2; ks++) {
        const int k0 = kc + ks * 16;
        unsigned af[4][4];
#pragma unroll
        for (int mt = 0; mt < 4; mt++) {
            int row = mt * 16 + (lane & 15);
            ldsm_x4(af[mt], su + (unsigned)(row * 512) +
                                ASWZ(row, (k0 + ((lane >> 4) << 3)) * 2));
        }
#pragma unroll
        for (int j = 0; j < NT; j++)
#pragma unroll
            for (int mt = 0; mt < 4; mt++)
                mma_f16(c[mt][j], af[mt], b + ks * 8 + 2 * j);
    }
}

// ---------------- main kernel ----------------
__global__ void __launch_bounds__(256, 2)
main_kernel(const float* __restrict__ x, const float* __restrict__ W1,
            const float* __restrict__ b1, const float* __restrict__ b2,
            const float* __restrict__ b3, const int* __restrict__ idx,
            float* __restrict__ out) {
    extern __shared__ char smem[];
    const uint32_t su = (uint32_t)__cvta_generic_to_shared(smem);

    const int a = blockIdx.y;
    const int n0 = blockIdx.x * TM;
    const int tid = threadIdx.x;
    const int wid = tid >> 5;
    const int lane = tid & 31;
    const int g = lane >> 2, tg = lane & 3;

    // n ownership (R13): layer2 = 4 tiles @ wid*4 (32 cols @ wid*32);
    // layer3 = 3 tiles @ wid*3 (wid<7), 4 tiles @ 21 (wid==7).
    const int nb2 = wid * 32;
    const int t3base = (wid < 7) ? wid * 3 : 21;
    const int nt3 = (wid < 7) ? 3 : 4;

    const uint2* base2 = g_w2f + (size_t)(a * 32 + wid * 4) * 256 + lane;
    const uint2* base3 = g_w3f + (size_t)(a * 25 + t3base) * 512 + lane;

    unsigned bcur[16], bnxt[16];

    // ---- prefetch chunk q=0 B into registers (hidden under layer1) ----
    load_b2(bcur, base2, 0);

    // ---- stage W1 ----
    float* s_w1 = (float*)(smem + OFF_W1);   // [12][128]
    for (int i = tid; i < NC * NH2; i += 256) s_w1[i] = W1[a * NC * NH2 + i];
    __syncthreads();                                       // barrier 1

    // ---- layer 1 (fp32 scalar): h1 = relu(xg@W1+b1) -> A plane (fp16) ----
    {
        const int t = tid & 63;
        const int hb = (tid >> 6) * 32;
        const int* idxa = idx + a * NC;
        float xv[NC];
#pragma unroll
        for (int c = 0; c < NC; c++)
            xv[c] = __ldg(&x[(size_t)(n0 + t) * NL + __ldg(&idxa[c])]);
        float acc[32];
#pragma unroll
        for (int j = 0; j < 32; j++) acc[j] = __ldg(&b1[a * NH2 + hb + j]);
#pragma unroll
        for (int c = 0; c < NC; c++) {
            const float4* wr = (const float4*)(s_w1 + c * NH2 + hb);
#pragma unroll
            for (int q = 0; q < 8; q++) {
                float4 w = wr[q];
                acc[q * 4 + 0] = fmaf(xv[c], w.x, acc[q * 4 + 0]);
                acc[q * 4 + 1] = fmaf(xv[c], w.y, acc[q * 4 + 1]);
                acc[q * 4 + 2] = fmaf(xv[c], w.z, acc[q * 4 + 2]);
                acc[q * 4 + 3] = fmaf(xv[c], w.w, acc[q * 4 + 3]);
            }
        }
        char* rowp = smem + (size_t)t * 512;
#pragma unroll
        for (int q = 0; q < 16; q++) {
            float v0 = fmaxf(acc[2 * q], 0.0f), v1 = fmaxf(acc[2 * q + 1], 0.0f);
            *(uint32_t*)(rowp + ASWZ(t, hb * 2 + q * 4)) = pack2h(v0, v1);
        }
    }
    __syncthreads();                                       // barrier 2: A2 ready

    float cacc[4][4][4];
#pragma unroll
    for (int mt = 0; mt < 4; mt++)
#pragma unroll
        for (int j = 0; j < 4; j++)
#pragma unroll
            for (int q = 0; q < 4; q++) cacc[mt][j][q] = 0.0f;

    // ---- layer 2: chunks q=0..3, B prefetch distance 1, NO barriers ----
#pragma unroll
    for (int q = 0; q < 4; q++) {
        if (q < 3) load_b2(bnxt, base2, q + 1);
        else       load_b3(bnxt, base3, 0, nt3);           // layer3 chunk 0
        gemm_chunk<4>(cacc, su, bcur, q * 32, lane);
#pragma unroll
        for (int r = 0; r < 16; r++) bcur[r] = bnxt[r];    // renamed by unroll
    }

    // ---- epilogue 2: bias+relu -> A3 plane (overwrites A2, fp16) ----
    __syncthreads();                                       // barrier 3: A2 reads done
    {
#pragma unroll
        for (int mt = 0; mt < 4; mt++) {
#pragma unroll
            for (int j = 0; j < 4; j++) {
                int col = nb2 + j * 8 + tg * 2;
                float bb0 = __ldg(&b2[a * NH + col]);
                float bb1 = __ldg(&b2[a * NH + col + 1]);
                int r0 = mt * 16 + g;
#pragma unroll
                for (int half = 0; half < 2; half++) {
                    int r = r0 + half * 8;
                    float v0 = fmaxf(cacc[mt][j][2 * half + 0] + bb0, 0.0f);
                    float v1 = fmaxf(cacc[mt][j][2 * half + 1] + bb1, 0.0f);
                    *(uint32_t*)(smem + (size_t)r * 512 + ASWZ(r, col * 2)) =
                        pack2h(v0, v1);
                }
            }
        }
    }
    __syncthreads();                                       // barrier 4: A3 ready

#pragma unroll
    for (int mt = 0; mt < 4; mt++)
#pragma unroll
        for (int j = 0; j < 4; j++)
#pragma unroll
            for (int q = 0; q < 4; q++) cacc[mt][j][q] = 0.0f;

    // ---- layer 3: chunks c=0..7, B prefetch distance 1, NO barriers ----
#pragma unroll
    for (int c = 0; c < 8; c++) {
        if (c < 7) load_b3(bnxt, base3, c + 1, nt3);
        if (nt3 == 3) gemm_chunk<3>(cacc, su, bcur, c * 32, lane);
        else          gemm_chunk<4>(cacc, su, bcur, c * 32, lane);
#pragma unroll
        for (int r = 0; r < 16; r++) bcur[r] = bnxt[r];
    }

    // ---- epilogue 3: bias add, store fragments directly (f32 out) ----
    {
#pragma unroll
        for (int mt = 0; mt < 4; mt++) {
#pragma unroll
            for (int j = 0; j < 4; j++) {
                if (j < nt3) {
                    int col = (t3base + j) * 8 + tg * 2;
                    float bb0 = __ldg(&b3[a * NF + col]);
                    float bb1 = __ldg(&b3[a * NF + col + 1]);
                    int r0 = mt * 16 + g;
#pragma unroll
                    for (int half = 0; half < 2; half++) {
                        int r = r0 + half * 8;
                        float2 v = make_float2(cacc[mt][j][2 * half + 0] + bb0,
                                               cacc[mt][j][2 * half + 1] + bb1);
                        *(float2*)&out[((size_t)(n0 + r) * NA + a) * NF + col] = v;
                    }
                }
            }
        }
    }
}

// ---------------- launch ----------------
extern "C" void kernel_launch(void* const* d_in, const int* in_sizes, int n_in,
                              void* d_out, int out_size) {
    const float *x = nullptr, *W1 = nullptr, *b1 = nullptr, *W2 = nullptr,
                *b2 = nullptr, *W3 = nullptr, *b3 = nullptr;
    const int* idx = nullptr;
    for (int i = 0; i < n_in; i++) {
        switch (in_sizes[i]) {
            case NTOK * NL:     x   = (const float*)d_in[i]; break;
            case NA * NC * NH2: W1  = (const float*)d_in[i]; break;
            case NA * NH2:      b1  = (const float*)d_in[i]; break;
            case NA * NH2 * NH: W2  = (const float*)d_in[i]; break;
            case NA * NH:       b2  = (const float*)d_in[i]; break;
            case NA * NH * NF:  W3  = (const float*)d_in[i]; break;
            case NA * NF:       b3  = (const float*)d_in[i]; break;
            case NA * NC:       idx = (const int*)d_in[i];   break;
            default: break;
        }
    }

    prep_w<<<(N_F2 + N_F3 + 255) / 256, 256>>>(W2, W3);

    cudaFuncSetAttribute(main_kernel,
                         cudaFuncAttributeMaxDynamicSharedMemorySize, SMEM_REQ);
    dim3 grid(NTOK / TM, NA);
    main_kernel<<<grid, 256, SMEM_REQ>>>(x, W1, b1, b2, b3, idx, (float*)d_out);
}